// round 2
// baseline (speedup 1.0000x reference)
#include <cuda_runtime.h>
#include <cuda_bf16.h>

#define EDIM 256
#define KCODES 1024
#define HWSZ 1024
#define BATCH 32
#define NROWS (BATCH*HWSZ)          // 32768

#define BR 128                       // rows (hw positions) per block
#define CHUNK 64                     // codes per smem chunk
#define NCHUNK (KCODES/CHUNK)        // 16
#define NTHREADS 256
#define NBLOCKS (NROWS/BR)           // 256

// smem byte layout. Strides chosen so (stride mod 128) == 16 -> conflict-free ldmatrix,
// and divisible by 16 for vectorized stores.
#define SA_STRIDE 272                // bytes per c-row of x tile: 128 hw * 2B + 16 pad
#define SB_STRIDE 528                // bytes per code-row:        256 c  * 2B + 16 pad
#define OFF_SB   (EDIM*SA_STRIDE)               // 69632
#define OFF_CBN  (OFF_SB + CHUNK*SB_STRIDE)     // 103424
#define OFF_XN   (OFF_CBN + KCODES*4)           // 107520
#define OFF_RED  (OFF_XN + BR*4)                // 108032  (4 warps x 128 rows partial mins)
#define OFF_WS   (OFF_RED + 4*BR*4)             // 110080
#define SMEM_BYTES (OFF_WS + 64)                // 110144

__device__ __nv_bfloat16 g_cb[KCODES*EDIM];
__device__ float g_cbnorm[KCODES];
__device__ float g_partial[NBLOCKS];

__device__ __forceinline__ unsigned s2u(const void* p) {
    return static_cast<unsigned>(__cvta_generic_to_shared(p));
}

__device__ __forceinline__ void ldsm4t(unsigned addr, unsigned &r0, unsigned &r1,
                                       unsigned &r2, unsigned &r3) {
    asm volatile("ldmatrix.sync.aligned.m8n8.x4.trans.shared.b16 {%0,%1,%2,%3}, [%4];"
                 : "=r"(r0), "=r"(r1), "=r"(r2), "=r"(r3) : "r"(addr));
}

__device__ __forceinline__ void ldsm2(unsigned addr, unsigned &r0, unsigned &r1) {
    asm volatile("ldmatrix.sync.aligned.m8n8.x2.shared.b16 {%0,%1}, [%2];"
                 : "=r"(r0), "=r"(r1) : "r"(addr));
}

__device__ __forceinline__ void mma16816(float &c0, float &c1, float &c2, float &c3,
                                         unsigned a0, unsigned a1, unsigned a2, unsigned a3,
                                         unsigned b0, unsigned b1) {
    asm volatile("mma.sync.aligned.m16n8k16.row.col.f32.bf16.bf16.f32 "
                 "{%0,%1,%2,%3}, {%4,%5,%6,%7}, {%8,%9}, {%0,%1,%2,%3};"
                 : "+f"(c0), "+f"(c1), "+f"(c2), "+f"(c3)
                 : "r"(a0), "r"(a1), "r"(a2), "r"(a3), "r"(b0), "r"(b1));
}

// ---------------- prep: codebook fp32 -> bf16 + fp32 row norms ----------------
__global__ void prep_kernel(const float* __restrict__ cb) {
    int w = threadIdx.x >> 5, lane = threadIdx.x & 31;
    #pragma unroll
    for (int rep = 0; rep < 2; rep++) {
        int code = blockIdx.x * 16 + w * 2 + rep;
        const float4* src = reinterpret_cast<const float4*>(cb + code * EDIM);
        float s = 0.f;
        #pragma unroll
        for (int q = 0; q < 2; q++) {
            int i4 = q * 32 + lane;
            float4 v = src[i4];
            s += v.x * v.x + v.y * v.y + v.z * v.z + v.w * v.w;
            __nv_bfloat162 p0 = __float22bfloat162_rn(make_float2(v.x, v.y));
            __nv_bfloat162 p1 = __float22bfloat162_rn(make_float2(v.z, v.w));
            *reinterpret_cast<__nv_bfloat162*>(&g_cb[code * EDIM + i4 * 4])     = p0;
            *reinterpret_cast<__nv_bfloat162*>(&g_cb[code * EDIM + i4 * 4 + 2]) = p1;
        }
        #pragma unroll
        for (int off = 16; off; off >>= 1) s += __shfl_xor_sync(0xffffffffu, s, off);
        if (lane == 0) g_cbnorm[code] = s;
    }
}

// ---------------- main: copy + distance GEMM + per-row min ----------------
__global__ __launch_bounds__(NTHREADS, 2)
void vq_kernel(const float* __restrict__ x, float* __restrict__ out, int write_out) {
    extern __shared__ unsigned char smem[];
    const int tid = threadIdx.x;
    const int lane = tid & 31;
    const int w = tid >> 5;
    const int wr = w & 1;       // row half: rows wr*64 .. +63
    const int wc = w >> 1;      // col quarter within 64-code chunk: cols wc*16 .. +15

    const int bi = blockIdx.x;
    const int b = bi >> 3;
    const int hw0 = (bi & 7) << 7;

    // ---- Phase 1: load x tile [c=256][hw=128], copy to out, store bf16 transposed ----
    const float* xb = x + (long)b * EDIM * HWSZ + hw0;
    float* ob = out + (long)b * EDIM * HWSZ + hw0;
    #pragma unroll
    for (int it = 0; it < 32; it++) {
        int item = it * NTHREADS + tid;
        int j4 = item & 31;          // lane-contiguous -> coalesced 512B/warp
        int c  = item >> 5;
        float4 v = *reinterpret_cast<const float4*>(xb + c * HWSZ + j4 * 4);
        if (write_out) *reinterpret_cast<float4*>(ob + c * HWSZ + j4 * 4) = v;
        __nv_bfloat162 p0 = __float22bfloat162_rn(make_float2(v.x, v.y));
        __nv_bfloat162 p1 = __float22bfloat162_rn(make_float2(v.z, v.w));
        unsigned char* dst = smem + c * SA_STRIDE + j4 * 8;
        *reinterpret_cast<__nv_bfloat162*>(dst)     = p0;
        *reinterpret_cast<__nv_bfloat162*>(dst + 4) = p1;
    }
    // stage codebook norms to smem (1024 floats)
    reinterpret_cast<float4*>(smem + OFF_CBN)[tid] =
        *reinterpret_cast<const float4*>(&g_cbnorm[tid * 4]);
    __syncthreads();

    // ---- Phase 2: per-row ||x||^2 (from bf16 tile; error << tolerance) ----
    float* sxn = reinterpret_cast<float*>(smem + OFF_XN);
    if (tid < BR) {
        float s0 = 0.f, s1 = 0.f;
        #pragma unroll 8
        for (int c = 0; c < EDIM; c += 2) {
            float v0 = __bfloat162float(*reinterpret_cast<const __nv_bfloat16*>(
                smem + c * SA_STRIDE + tid * 2));
            float v1 = __bfloat162float(*reinterpret_cast<const __nv_bfloat16*>(
                smem + (c + 1) * SA_STRIDE + tid * 2));
            s0 = fmaf(v0, v0, s0);
            s1 = fmaf(v1, v1, s1);
        }
        sxn[tid] = s0 + s1;
    }

    // ---- Phase 3: chunked GEMM with running per-row min ----
    const int c_off  = (lane & 7) + ((lane >> 4) & 1) * 8;
    const int hw_off = ((lane >> 3) & 1) * 8;
    const unsigned smem_u = s2u(smem);
    const unsigned aBase = smem_u + (unsigned)(c_off * SA_STRIDE)
                         + (unsigned)((wr * 64 + hw_off) * 2);
    const unsigned bBase = smem_u + OFF_SB
                         + (unsigned)((wc * 16 + (lane & 7)) * SB_STRIDE)
                         + (unsigned)(((lane >> 3) & 1) * 16);

    float rmin[8];
    #pragma unroll
    for (int j = 0; j < 8; j++) rmin[j] = 1e30f;

    const float* scb = reinterpret_cast<const float*>(smem + OFF_CBN);

    for (int ch = 0; ch < NCHUNK; ch++) {
        // stage codebook chunk [64 codes][256 c] bf16 into smem
        const uint4* src = reinterpret_cast<const uint4*>(g_cb) + (long)ch * CHUNK * 32;
        #pragma unroll
        for (int i = 0; i < 8; i++) {
            int item = i * NTHREADS + tid;
            int r = item >> 5, c8 = item & 31;
            uint4 vv = src[r * 32 + c8];
            *reinterpret_cast<uint4*>(smem + OFF_SB + r * SB_STRIDE + c8 * 16) = vv;
        }
        __syncthreads();

        float acc[4][2][4];
        #pragma unroll
        for (int rt = 0; rt < 4; rt++)
            #pragma unroll
            for (int ct = 0; ct < 2; ct++)
                #pragma unroll
                for (int i = 0; i < 4; i++) acc[rt][ct][i] = 0.f;

        #pragma unroll 4
        for (int ks = 0; ks < 16; ks++) {
            unsigned a[4][4];
            #pragma unroll
            for (int rt = 0; rt < 4; rt++)
                ldsm4t(aBase + rt * 32 + ks * (16 * SA_STRIDE),
                       a[rt][0], a[rt][1], a[rt][2], a[rt][3]);
            #pragma unroll
            for (int ct = 0; ct < 2; ct++) {
                unsigned b0, b1;
                ldsm2(bBase + ct * (8 * SB_STRIDE) + ks * 32, b0, b1);
                #pragma unroll
                for (int rt = 0; rt < 4; rt++)
                    mma16816(acc[rt][ct][0], acc[rt][ct][1], acc[rt][ct][2], acc[rt][ct][3],
                             a[rt][0], a[rt][1], a[rt][2], a[rt][3], b0, b1);
            }
        }

        // epilogue: d = ||e||^2 - 2 x.e ; fold into per-row running min
        int kb = ch * CHUNK + wc * 16 + (lane & 3) * 2;
        #pragma unroll
        for (int ct = 0; ct < 2; ct++) {
            float cn0 = scb[kb + ct * 8];
            float cn1 = scb[kb + ct * 8 + 1];
            #pragma unroll
            for (int rt = 0; rt < 4; rt++) {
                float d0 = fmaf(-2.f, acc[rt][ct][0], cn0);
                float d1 = fmaf(-2.f, acc[rt][ct][1], cn1);
                float d2 = fmaf(-2.f, acc[rt][ct][2], cn0);
                float d3 = fmaf(-2.f, acc[rt][ct][3], cn1);
                rmin[rt * 2]     = fminf(rmin[rt * 2],     fminf(d0, d1));
                rmin[rt * 2 + 1] = fminf(rmin[rt * 2 + 1], fminf(d2, d3));
            }
        }
        __syncthreads();   // protect sB before next chunk's overwrite
    }

    // ---- Phase 4: reduce ----
    // (a) intra-warp: min across the 4 lanes of each quad (covers this warp's 8 cols)
    #pragma unroll
    for (int j = 0; j < 8; j++) {
        rmin[j] = fminf(rmin[j], __shfl_xor_sync(0xffffffffu, rmin[j], 1));
        rmin[j] = fminf(rmin[j], __shfl_xor_sync(0xffffffffu, rmin[j], 2));
    }
    // (b) publish per-row PARTIAL mins (each wc warp covered only 256 of 1024 codes)
    float* sred = reinterpret_cast<float*>(smem + OFF_RED);
    if ((lane & 3) == 0) {
        int g = lane >> 2;
        #pragma unroll
        for (int j = 0; j < 8; j++) {
            int row = wr * 64 + (j >> 1) * 16 + g + (j & 1) * 8;  // 0..127
            sred[wc * BR + row] = rmin[j];
        }
    }
    __syncthreads();
    // (c) cross-warp min per row, add ||x||^2 ONCE, then block-sum
    float* sws = reinterpret_cast<float*>(smem + OFF_WS);
    if (tid < BR) {
        float m = fminf(fminf(sred[tid],          sred[BR + tid]),
                        fminf(sred[2 * BR + tid], sred[3 * BR + tid]));
        float v = sxn[tid] + m;
        #pragma unroll
        for (int off = 16; off; off >>= 1) v += __shfl_xor_sync(0xffffffffu, v, off);
        if (lane == 0) sws[w] = v;
    }
    __syncthreads();
    if (tid == 0) {
        g_partial[bi] = sws[0] + sws[1] + sws[2] + sws[3];
    }
}

// ---------------- finish: deterministic final sum -> loss ----------------
__global__ void finish_kernel(float* out, int out_size) {
    if (threadIdx.x == 0) {
        double s = 0.0;
        for (int i = 0; i < NBLOCKS; i++) s += (double)g_partial[i];
        out[out_size - 1] = (float)(1.25 * s / (double)((long)NROWS * EDIM));
    }
}

extern "C" void kernel_launch(void* const* d_in, const int* in_sizes, int n_in,
                              void* d_out, int out_size) {
    const float* x  = (const float*)d_in[0];
    const float* cb = (const float*)d_in[1];
    if (n_in >= 2 && in_sizes[0] == KCODES * EDIM && in_sizes[1] == NROWS * EDIM) {
        const float* t = x; x = cb; cb = t;   // defensive input-order swap
    }
    cudaFuncSetAttribute(vq_kernel, cudaFuncAttributeMaxDynamicSharedMemorySize, SMEM_BYTES);

    int write_out = (out_size > NROWS * EDIM) ? 1 : 0;
    prep_kernel<<<64, 256>>>(cb);
    vq_kernel<<<NBLOCKS, NTHREADS, SMEM_BYTES>>>(x, (float*)d_out, write_out);
    finish_kernel<<<1, 32>>>((float*)d_out, out_size);
}

// round 4
// speedup vs baseline: 1.3512x; 1.3512x over previous
#include <cuda_runtime.h>
#include <cuda_bf16.h>
#include <cstdint>

#define EDIM 256
#define KCODES 1024
#define HWSZ 1024
#define BATCH 32
#define NROWS (BATCH*HWSZ)          // 32768

#define BM 128                       // rows (hw positions) per CTA
#define BN 128                       // codes per chunk
#define NCHUNK (KCODES/BN)           // 8
#define NTHREADS 256
#define NBLOCKS (NROWS/BM)           // 256

// smem strides: (stride mod 128)==16 -> conflict-free ldmatrix, 16B-divisible.
#define SA_STRIDE 272                // bytes per c-row of x tile: 128 hw * 2B + 16
#define SB_STRIDE 528                // bytes per code-row: 256 k * 2B + 16
#define B_BUF    (BN*SB_STRIDE)                 // 67584 per buffer
#define OFF_A    0
#define OFF_B    (EDIM*SA_STRIDE)               // 69632
#define OFF_CBN  (OFF_B + 2*B_BUF)              // 204800 (1024 fp32 code norms)
#define OFF_XN   (OFF_CBN + KCODES*4)           // 208896 (128 fp32 row norms)
#define OFF_RED  (OFF_XN + BM*4)                // 209408 (4 x 128 partial mins)
#define OFF_WS   (OFF_RED + 4*BM*4)             // 211456
#define SMEM_BYTES (OFF_WS + 64)                // 211520

__device__ __align__(16) __nv_bfloat16 g_cb[KCODES*EDIM];
__device__ float g_cbnorm[KCODES];
__device__ float g_partial[NBLOCKS];

// ----------------------------- helpers -----------------------------
__device__ __forceinline__ unsigned s2u(const void* p) {
    return static_cast<unsigned>(__cvta_generic_to_shared(p));
}
__device__ __forceinline__ void ldsm4t(unsigned addr, unsigned &r0, unsigned &r1,
                                       unsigned &r2, unsigned &r3) {
    asm volatile("ldmatrix.sync.aligned.m8n8.x4.trans.shared.b16 {%0,%1,%2,%3}, [%4];"
                 : "=r"(r0), "=r"(r1), "=r"(r2), "=r"(r3) : "r"(addr));
}
__device__ __forceinline__ void ldsm4(unsigned addr, unsigned &r0, unsigned &r1,
                                      unsigned &r2, unsigned &r3) {
    asm volatile("ldmatrix.sync.aligned.m8n8.x4.shared.b16 {%0,%1,%2,%3}, [%4];"
                 : "=r"(r0), "=r"(r1), "=r"(r2), "=r"(r3) : "r"(addr));
}
__device__ __forceinline__ void mma16816(float &c0, float &c1, float &c2, float &c3,
                                         unsigned a0, unsigned a1, unsigned a2, unsigned a3,
                                         unsigned b0, unsigned b1) {
    asm volatile("mma.sync.aligned.m16n8k16.row.col.f32.bf16.bf16.f32 "
                 "{%0,%1,%2,%3}, {%4,%5,%6,%7}, {%8,%9}, {%0,%1,%2,%3};"
                 : "+f"(c0), "+f"(c1), "+f"(c2), "+f"(c3)
                 : "r"(a0), "r"(a1), "r"(a2), "r"(a3), "r"(b0), "r"(b1));
}
#define CP_ASYNC16(dst, src) \
    asm volatile("cp.async.cg.shared.global [%0], [%1], 16;" \
                 :: "r"(dst), "l"(src) : "memory")
#define CP_COMMIT() asm volatile("cp.async.commit_group;" ::: "memory")
#define CP_WAIT0()  asm volatile("cp.async.wait_group 0;" ::: "memory")

// ---------------- prep: codebook fp32 -> bf16 + fp32 row norms ----------------
__global__ void prep_kernel(const float* __restrict__ cb) {
    int w = threadIdx.x >> 5, lane = threadIdx.x & 31;
    int code = blockIdx.x * 8 + w;
    const float4* src = reinterpret_cast<const float4*>(cb + code * EDIM);
    float s = 0.f;
    #pragma unroll
    for (int q = 0; q < 2; q++) {
        int i4 = q * 32 + lane;
        float4 v = src[i4];
        s += v.x * v.x + v.y * v.y + v.z * v.z + v.w * v.w;
        __nv_bfloat162 p0 = __float22bfloat162_rn(make_float2(v.x, v.y));
        __nv_bfloat162 p1 = __float22bfloat162_rn(make_float2(v.z, v.w));
        *reinterpret_cast<__nv_bfloat162*>(&g_cb[code * EDIM + i4 * 4])     = p0;
        *reinterpret_cast<__nv_bfloat162*>(&g_cb[code * EDIM + i4 * 4 + 2]) = p1;
    }
    #pragma unroll
    for (int off = 16; off; off >>= 1) s += __shfl_xor_sync(0xffffffffu, s, off);
    if (lane == 0) g_cbnorm[code] = s;
}

// ---------------- main: copy + distance GEMM + per-row min ----------------
__global__ __launch_bounds__(NTHREADS, 1)
void vq_kernel(const float* __restrict__ x, float* __restrict__ out, int write_out) {
    extern __shared__ __align__(16) unsigned char smem[];
    const int tid = threadIdx.x;
    const int lane = tid & 31;
    const int w = tid >> 5;
    const int wr = w & 1;        // row half: rows wr*64 .. +63
    const int wc = w >> 1;       // col quarter of 128-code chunk: cols wc*32 .. +31
    const unsigned smem_u = s2u(smem);

    const int bi = blockIdx.x;
    const int b = bi >> 3;
    const int hw0 = (bi & 7) << 7;

    // ---- prefetch B chunk 0 (overlaps with x-tile load below) ----
    {
        const __nv_bfloat16* gsrc = g_cb;   // chunk 0
        unsigned sdst = smem_u + OFF_B;     // buf 0
        #pragma unroll
        for (int i = 0; i < 16; i++) {
            int item = i * NTHREADS + tid;
            int r = item >> 5, k16 = item & 31;
            CP_ASYNC16(sdst + r * SB_STRIDE + k16 * 16, gsrc + r * EDIM + k16 * 8);
        }
        CP_COMMIT();
    }

    // ---- Phase 1: load x tile [c=256][hw=128], copy to out, store bf16 ----
    const float* xb = x + (long)b * EDIM * HWSZ + hw0;
    float* ob = out + (long)b * EDIM * HWSZ + hw0;
    #pragma unroll 8
    for (int it = 0; it < 32; it++) {
        int item = it * NTHREADS + tid;
        int j4 = item & 31;          // hw/4, lane-contiguous -> coalesced
        int c  = item >> 5;
        float4 v = *reinterpret_cast<const float4*>(xb + c * HWSZ + j4 * 4);
        if (write_out) *reinterpret_cast<float4*>(ob + c * HWSZ + j4 * 4) = v;
        __nv_bfloat162 p0 = __float22bfloat162_rn(make_float2(v.x, v.y));
        __nv_bfloat162 p1 = __float22bfloat162_rn(make_float2(v.z, v.w));
        unsigned char* dst = smem + c * SA_STRIDE + j4 * 8;
        *reinterpret_cast<__nv_bfloat162*>(dst)     = p0;
        *reinterpret_cast<__nv_bfloat162*>(dst + 4) = p1;
    }
    // stage codebook norms (1024 fp32)
    reinterpret_cast<float4*>(smem + OFF_CBN)[tid] =
        *reinterpret_cast<const float4*>(&g_cbnorm[tid * 4]);
    __syncthreads();

    // ---- Phase 2: per-row ||x||^2 from bf16 tile ----
    float* sxn = reinterpret_cast<float*>(smem + OFF_XN);
    if (tid < BM) {
        float s0 = 0.f, s1 = 0.f;
        #pragma unroll 8
        for (int c = 0; c < EDIM; c += 2) {
            float v0 = __bfloat162float(*reinterpret_cast<const __nv_bfloat16*>(
                smem + c * SA_STRIDE + tid * 2));
            float v1 = __bfloat162float(*reinterpret_cast<const __nv_bfloat16*>(
                smem + (c + 1) * SA_STRIDE + tid * 2));
            s0 = fmaf(v0, v0, s0);
            s1 = fmaf(v1, v1, s1);
        }
        sxn[tid] = s0 + s1;
    }

    // ---- Phase 3: chunked GEMM, double-buffered cp.async B, per-row min ----
    const int c_off  = (lane & 7) + ((lane >> 4) & 1) * 8;
    const int hw_off = ((lane >> 3) & 1) * 8;
    const unsigned aBase = smem_u + (unsigned)(c_off * SA_STRIDE)
                         + (unsigned)((wr * 64 + hw_off) * 2);
    const unsigned bLane = (unsigned)((wc * 32 + (lane & 7) + ((lane >> 4) & 1) * 8)
                                      * SB_STRIDE)
                         + (unsigned)(((lane >> 3) & 1) * 16);
    const float* scbn = reinterpret_cast<const float*>(smem + OFF_CBN);

    float rmin[8];
    #pragma unroll
    for (int j = 0; j < 8; j++) rmin[j] = 1e30f;

    for (int ch = 0; ch < NCHUNK; ch++) {
        CP_WAIT0();            // chunk ch staged (this thread's groups)
        __syncthreads();       // all threads staged + prev buffer free

        // prefetch chunk ch+1 into the other buffer (async, overlapped)
        if (ch + 1 < NCHUNK) {
            const __nv_bfloat16* gsrc = g_cb + (long)(ch + 1) * BN * EDIM;
            unsigned sdst = smem_u + OFF_B + (unsigned)((ch + 1) & 1) * B_BUF;
            #pragma unroll
            for (int i = 0; i < 16; i++) {
                int item = i * NTHREADS + tid;
                int r = item >> 5, k16 = item & 31;
                CP_ASYNC16(sdst + r * SB_STRIDE + k16 * 16, gsrc + r * EDIM + k16 * 8);
            }
            CP_COMMIT();
        }

        const unsigned bBase = smem_u + OFF_B + (unsigned)(ch & 1) * B_BUF + bLane;

        float acc[2][4][4];    // [row tile pair handled as rt loop]{...}
        // full acc: 4 row tiles x 4 n8 tiles x 4 regs = 64
        float accf[4][4][4];
        #pragma unroll
        for (int rt = 0; rt < 4; rt++)
            #pragma unroll
            for (int nt = 0; nt < 4; nt++)
                #pragma unroll
                for (int i = 0; i < 4; i++) accf[rt][nt][i] = 0.f;
        (void)acc;

        #pragma unroll 4
        for (int ks = 0; ks < 16; ks++) {
            unsigned a[4][4];
            #pragma unroll
            for (int rt = 0; rt < 4; rt++)
                ldsm4t(aBase + rt * 32 + ks * (16 * SA_STRIDE),
                       a[rt][0], a[rt][1], a[rt][2], a[rt][3]);
            #pragma unroll
            for (int ct = 0; ct < 2; ct++) {
                unsigned b0, b1, b2, b3;   // 16 codes: two n8 tiles
                ldsm4(bBase + ct * (16 * SB_STRIDE) + ks * 32, b0, b1, b2, b3);
                #pragma unroll
                for (int rt = 0; rt < 4; rt++) {
                    mma16816(accf[rt][ct*2][0], accf[rt][ct*2][1],
                             accf[rt][ct*2][2], accf[rt][ct*2][3],
                             a[rt][0], a[rt][1], a[rt][2], a[rt][3], b0, b1);
                    mma16816(accf[rt][ct*2+1][0], accf[rt][ct*2+1][1],
                             accf[rt][ct*2+1][2], accf[rt][ct*2+1][3],
                             a[rt][0], a[rt][1], a[rt][2], a[rt][3], b2, b3);
                }
            }
        }

        // epilogue: d = ||e||^2 - 2 x.e ; fold into per-row running min
        int kb = ch * BN + wc * 32 + (lane & 3) * 2;
        #pragma unroll
        for (int nt = 0; nt < 4; nt++) {
            float cn0 = scbn[kb + nt * 8];
            float cn1 = scbn[kb + nt * 8 + 1];
            #pragma unroll
            for (int rt = 0; rt < 4; rt++) {
                float d0 = fmaf(-2.f, accf[rt][nt][0], cn0);
                float d1 = fmaf(-2.f, accf[rt][nt][1], cn1);
                float d2 = fmaf(-2.f, accf[rt][nt][2], cn0);
                float d3 = fmaf(-2.f, accf[rt][nt][3], cn1);
                rmin[rt * 2]     = fminf(rmin[rt * 2],     fminf(d0, d1));
                rmin[rt * 2 + 1] = fminf(rmin[rt * 2 + 1], fminf(d2, d3));
            }
        }
    }

    // ---- Phase 4: reduce ----
    #pragma unroll
    for (int j = 0; j < 8; j++) {
        rmin[j] = fminf(rmin[j], __shfl_xor_sync(0xffffffffu, rmin[j], 1));
        rmin[j] = fminf(rmin[j], __shfl_xor_sync(0xffffffffu, rmin[j], 2));
    }
    float* sred = reinterpret_cast<float*>(smem + OFF_RED);
    if ((lane & 3) == 0) {
        int g = lane >> 2;
        #pragma unroll
        for (int j = 0; j < 8; j++) {
            int row = wr * 64 + (j >> 1) * 16 + g + (j & 1) * 8;  // 0..127
            sred[wc * BM + row] = rmin[j];
        }
    }
    __syncthreads();
    float* sws = reinterpret_cast<float*>(smem + OFF_WS);
    if (tid < BM) {
        float m = fminf(fminf(sred[tid],          sred[BM + tid]),
                        fminf(sred[2 * BM + tid], sred[3 * BM + tid]));
        float v = sxn[tid] + m;
        #pragma unroll
        for (int off = 16; off; off >>= 1) v += __shfl_xor_sync(0xffffffffu, v, off);
        if (lane == 0) sws[w] = v;
    }
    __syncthreads();
    if (tid == 0) g_partial[bi] = sws[0] + sws[1] + sws[2] + sws[3];
}

// ---------------- finish: deterministic tree sum -> loss ----------------
__global__ void finish_kernel(float* out, int out_size) {
    __shared__ double sd[NBLOCKS];
    int t = threadIdx.x;
    sd[t] = (double)g_partial[t];
    __syncthreads();
    #pragma unroll
    for (int off = NBLOCKS / 2; off; off >>= 1) {
        if (t < off) sd[t] += sd[t + off];
        __syncthreads();
    }
    if (t == 0)
        out[out_size - 1] = (float)(1.25 * sd[0] / (double)((long)NROWS * EDIM));
}

extern "C" void kernel_launch(void* const* d_in, const int* in_sizes, int n_in,
                              void* d_out, int out_size) {
    const float* x  = (const float*)d_in[0];
    const float* cb = (const float*)d_in[1];
    if (n_in >= 2 && in_sizes[0] == KCODES * EDIM && in_sizes[1] == NROWS * EDIM) {
        const float* t = x; x = cb; cb = t;   // defensive input-order swap
    }
    cudaFuncSetAttribute(vq_kernel, cudaFuncAttributeMaxDynamicSharedMemorySize, SMEM_BYTES);

    int write_out = (out_size > NROWS * EDIM) ? 1 : 0;
    prep_kernel<<<128, 256>>>(cb);
    vq_kernel<<<NBLOCKS, NTHREADS, SMEM_BYTES>>>(x, (float*)d_out, write_out);
    finish_kernel<<<1, NBLOCKS>>>((float*)d_out, out_size);
}